// round 7
// baseline (speedup 1.0000x reference)
#include <cuda_runtime.h>

#define NBATCH 16
#define NF     128
#define NT     4096
#define NS     4
#define TPB    256
#define PT     16          // TPB*PT == NT
#define GP     20          // padded group stride (16 data + 4 pad floats)
#define BUFSZ  (TPB * GP)  // 5120 floats = 20KB

__device__ __forceinline__ float fast_exp2(float x) {
    float r; asm("ex2.approx.ftz.f32 %0, %1;" : "=f"(r) : "f"(x)); return r;
}
__device__ __forceinline__ float fast_log2(float x) {
    float r; asm("lg2.approx.ftz.f32 %0, %1;" : "=f"(r) : "f"(x)); return r;
}

// padded smem float-address of logical element quad Q (elements 4Q..4Q+3)
__device__ __forceinline__ int qaddr(int Q) { return (Q >> 2) * GP + (Q & 3) * 4; }

__global__ __launch_bounds__(TPB, 5)
void mrpcen_kernel(const float* __restrict__ x,
                   const float* __restrict__ alpha_log,
                   const float* __restrict__ delta_log,
                   const float* __restrict__ r_log,
                   float* __restrict__ out)
{
    const int row  = blockIdx.x;        // b*NF + f
    const int f    = row & (NF - 1);
    const int b    = row >> 7;
    const int tid  = threadIdx.x;
    const int lane = tid & 31;
    const int w    = tid >> 5;

    __shared__ float buf0[BUFSZ];
    __shared__ float buf1[BUFSZ];
    __shared__ float wagg[NS][TPB / 32];

    // ---- problem-constant smoother coefficients (f32, as in reference) ----
    float s[NS], a[NS], a16[NS];
    {
        const float tv[NS] = {0.015f, 0.06f, 0.25f, 1.0f};
#pragma unroll
        for (int i = 0; i < NS; i++) {
            float tt = tv[i] * (44100.0f / 512.0f);
            float d2 = 2.0f * tt * tt;
            s[i] = (sqrtf(1.0f + 2.0f * d2) - 1.0f) / d2;
            a[i] = 1.0f - s[i];
            float t2 = a[i] * a[i], t4 = t2 * t2, t8 = t4 * t4;
            a16[i] = t8 * t8;
        }
    }

    const float al    = alpha_log[f];
    const float dl    = delta_log[f];
    const float rl    = r_log[f];
    const float nalpha = -__expf(al);
    const float delta  = __expf(dl);
    const float rr     = __expf(rl);
    const float delta_r = __expf(rr * dl);

    // ---- stage x: coalesced LDG.128 -> padded smem ----
    const float* xrow = x + (size_t)row * NT;
#pragma unroll
    for (int j = 0; j < 4; j++) {
        int Q = j * TPB + tid;
        float4 v = *reinterpret_cast<const float4*>(xrow + 4 * Q);
        *reinterpret_cast<float4*>(&buf0[qaddr(Q)]) = v;
    }
    __syncthreads();

    // each thread pulls its 16 contiguous elements (own padded group)
    float xv[PT];
#pragma unroll
    for (int q = 0; q < 4; q++) {
        float4 v = *reinterpret_cast<float4*>(&buf0[tid * GP + q * 4]);
        xv[4 * q + 0] = v.x; xv[4 * q + 1] = v.y;
        xv[4 * q + 2] = v.z; xv[4 * q + 3] = v.w;
    }

    // ---- pass 1 (scaled n-recurrence: n = a*n + x, m = s*n) + warp scans ----
    float bc[NS];
#pragma unroll
    for (int si = 0; si < NS; si++) {
        float n = 0.0f;
#pragma unroll
        for (int k = 0; k < PT; k++)
            n = fmaf(a[si], n, xv[k]);          // 1 FMA per element
        if (tid == 0)                            // boundary: n_in = x[0]/s
            n = fmaf(a16[si], __fdividef(xv[0], s[si]), n);
        float c = a16[si];
#pragma unroll
        for (int d = 1; d <= 16; d <<= 1) {
            float up = __shfl_up_sync(0xffffffffu, n, d);
            if (lane >= d) n = fmaf(c, up, n);
            c = c * c;
        }
        bc[si] = n;
        if (lane == 31) wagg[si][w] = n;
    }
    __syncthreads();

    // ---- cross-warp: one segmented 32-lane scan handles 4 rates x 8 warps ----
    if (w == 0) {
        const int gsi = lane >> 3, gl = lane & 7;
        float v = wagg[gsi][gl];
        float tt = (gsi == 0) ? (0.015f * (44100.0f / 512.0f)) :
                   (gsi == 1) ? (0.06f  * (44100.0f / 512.0f)) :
                   (gsi == 2) ? (0.25f  * (44100.0f / 512.0f)) :
                                (1.0f   * (44100.0f / 512.0f));
        float d2 = 2.0f * tt * tt;
        float aa = 1.0f - (sqrtf(1.0f + 2.0f * d2) - 1.0f) / d2;
        float c = aa;
#pragma unroll
        for (int i = 0; i < 9; i++) c = c * c;   // a^512
#pragma unroll
        for (int d = 1; d <= 4; d <<= 1) {
            float up = __shfl_up_sync(0xffffffffu, v, d);
            if (gl >= d) v = fmaf(c, up, v);
            c = c * c;
        }
        wagg[gsi][gl] = v;                       // inclusive warp prefix (n-space)
    }
    __syncthreads();

    // ---- per-thread incoming state per rate (n-space) ----
    float minv[NS];
#pragma unroll
    for (int si = 0; si < NS; si++) {
        float Lprev = __shfl_up_sync(0xffffffffu, bc[si], 1);
        if (tid == 0) {
            minv[si] = __fdividef(xv[0], s[si]);   // n_in = x[0]/s
        } else {
            float P = (w > 0) ? wagg[si][w - 1] : 0.0f;
            float a16l = fast_exp2((float)(16 * lane) * fast_log2(a[si]));
            minv[si] = fmaf(a16l, P, (lane > 0) ? Lprev : 0.0f);
        }
    }

    // ---- pass 2: two rate-pairs interleaved, fused PCEN, staged stores ----
#pragma unroll
    for (int pp = 0; pp < 2; pp++) {
        const int s0i = 2 * pp, s1i = 2 * pp + 1;
        float n0 = minv[s0i], n1 = minv[s1i];
#pragma unroll
        for (int q = 0; q < 4; q++) {
            float t0[4], t1[4];
#pragma unroll
            for (int e = 0; e < 4; e++) {
                const int k = q * 4 + e;
                // rate A
                n0 = fmaf(a[s0i], n0, xv[k]);
                float u0  = fmaf(s[s0i], n0, 1e-5f);                 // eps + m
                float sm0 = fast_exp2(nalpha * fast_log2(u0));       // u^-alpha
                float v0  = fmaf(xv[k], sm0, delta);
                t0[e] = fast_exp2(rr * fast_log2(v0)) - delta_r;
                // rate B (independent chain, interleaved for ILP)
                n1 = fmaf(a[s1i], n1, xv[k]);
                float u1  = fmaf(s[s1i], n1, 1e-5f);
                float sm1 = fast_exp2(nalpha * fast_log2(u1));
                float v1  = fmaf(xv[k], sm1, delta);
                t1[e] = fast_exp2(rr * fast_log2(v1)) - delta_r;
            }
            float4 o0, o1;
            o0.x = t0[0]; o0.y = t0[1]; o0.z = t0[2]; o0.w = t0[3];
            o1.x = t1[0]; o1.y = t1[1]; o1.z = t1[2]; o1.w = t1[3];
            *reinterpret_cast<float4*>(&buf0[tid * GP + q * 4]) = o0;
            *reinterpret_cast<float4*>(&buf1[tid * GP + q * 4]) = o1;
        }
        __syncthreads();

        // drain both rates with coalesced STG.128
#pragma unroll
        for (int h = 0; h < 2; h++) {
            const int si = 2 * pp + h;
            const float* sb = h ? buf1 : buf0;
            float* orow = out + (((size_t)b * NS + si) * NF + f) * (size_t)NT;
#pragma unroll
            for (int j = 0; j < 4; j++) {
                int Q = j * TPB + tid;
                float4 v = *reinterpret_cast<const float4*>(&sb[qaddr(Q)]);
                *reinterpret_cast<float4*>(orow + 4 * Q) = v;
            }
        }
        if (pp == 0) __syncthreads();   // protect buffers before pair B rewrites
    }
}

extern "C" void kernel_launch(void* const* d_in, const int* in_sizes, int n_in,
                              void* d_out, int out_size) {
    const float* x         = (const float*)d_in[0];
    const float* alpha_log = (const float*)d_in[1];
    const float* delta_log = (const float*)d_in[2];
    const float* r_log     = (const float*)d_in[3];
    float* out             = (float*)d_out;
    (void)in_sizes; (void)n_in; (void)out_size;

    dim3 grid(NBATCH * NF);   // 2048 blocks: one per (b, f) row
    dim3 block(TPB);
    mrpcen_kernel<<<grid, block>>>(x, alpha_log, delta_log, r_log, out);
}

// round 8
// speedup vs baseline: 1.0494x; 1.0494x over previous
#include <cuda_runtime.h>

#define NBATCH 16
#define NF     128
#define NT     4096
#define NS     4
#define TPB    256
#define PT     16          // TPB*PT == NT
#define GP     20          // padded group stride (16 data + 4 pad floats)
#define BUFSZ  (TPB * GP)  // 5120 floats = 20KB

__device__ __forceinline__ float fast_exp2(float x) {
    float r; asm("ex2.approx.ftz.f32 %0, %1;" : "=f"(r) : "f"(x)); return r;
}
__device__ __forceinline__ float fast_log2(float x) {
    float r; asm("lg2.approx.ftz.f32 %0, %1;" : "=f"(r) : "f"(x)); return r;
}

// Polynomial exp2 for the latency-tolerant final pow: magic-add round +
// deg-4 poly on f in [-0.5,0.5] + exact exponent splice (low 9 bits of
// 0x4B400000 are zero). Valid |t| < 126, max rel err ~4e-5.
__device__ __forceinline__ float poly_exp2(float t) {
    const float magic = 12582912.0f;           // 1.5 * 2^23
    float z  = t + magic;
    float zi = z - magic;
    float fr = t - zi;
    float p  = fmaf(0.00961812911f, fr, 0.05550410866f);
    p = fmaf(p, fr, 0.24022650700f);
    p = fmaf(p, fr, 0.69314718056f);
    p = fmaf(p, fr, 1.0f);
    return __uint_as_float(__float_as_uint(p) + (__float_as_uint(z) << 23));
}

// padded smem float-address of logical element quad Q (elements 4Q..4Q+3)
__device__ __forceinline__ int qaddr(int Q) { return (Q >> 2) * GP + (Q & 3) * 4; }

__global__ __launch_bounds__(TPB, 5)
void mrpcen_kernel(const float* __restrict__ x,
                   const float* __restrict__ alpha_log,
                   const float* __restrict__ delta_log,
                   const float* __restrict__ r_log,
                   float* __restrict__ out)
{
    const int row  = blockIdx.x;        // b*NF + f
    const int f    = row & (NF - 1);
    const int b    = row >> 7;
    const int tid  = threadIdx.x;
    const int lane = tid & 31;
    const int w    = tid >> 5;

    __shared__ float buf[2][BUFSZ];
    __shared__ float wagg[NS][TPB / 32];

    // ---- problem-constant smoother coefficients (f32, as in reference) ----
    float s[NS], a[NS], a16[NS];
    {
        const float tv[NS] = {0.015f, 0.06f, 0.25f, 1.0f};
#pragma unroll
        for (int i = 0; i < NS; i++) {
            float tt = tv[i] * (44100.0f / 512.0f);
            float d2 = 2.0f * tt * tt;
            s[i] = (sqrtf(1.0f + 2.0f * d2) - 1.0f) / d2;
            a[i] = 1.0f - s[i];
            float t2 = a[i] * a[i], t4 = t2 * t2, t8 = t4 * t4;
            a16[i] = t8 * t8;
        }
    }

    const float al    = alpha_log[f];
    const float dl    = delta_log[f];
    const float rl    = r_log[f];
    const float alpha = __expf(al);
    const float delta = __expf(dl);
    const float rr    = __expf(rl);
    const float delta_r = __expf(rr * dl);

    // ---- stage x: coalesced LDG.128 -> padded smem ----
    const float* xrow = x + (size_t)row * NT;
#pragma unroll
    for (int j = 0; j < 4; j++) {
        int Q = j * TPB + tid;
        float4 v = *reinterpret_cast<const float4*>(xrow + 4 * Q);
        *reinterpret_cast<float4*>(&buf[0][qaddr(Q)]) = v;
    }
    __syncthreads();

    // each thread pulls its 16 contiguous elements (own padded group)
    float xv[PT];
#pragma unroll
    for (int q = 0; q < 4; q++) {
        float4 v = *reinterpret_cast<float4*>(&buf[0][tid * GP + q * 4]);
        xv[4 * q + 0] = v.x; xv[4 * q + 1] = v.y;
        xv[4 * q + 2] = v.z; xv[4 * q + 3] = v.w;
    }

    // ---- pass 1 + register scans, all 4 rates ----
    float bc[NS];
#pragma unroll
    for (int si = 0; si < NS; si++) {
        float bcar = 0.0f;
#pragma unroll
        for (int k = 0; k < PT; k++)
            bcar = fmaf(a[si], bcar, s[si] * xv[k]);
        if (tid == 0)                       // fold m[0]=x[0] boundary (a+s==1)
            bcar = fmaf(a16[si], xv[0], bcar);
        float c = a16[si];
#pragma unroll
        for (int d = 1; d <= 16; d <<= 1) {
            float up = __shfl_up_sync(0xffffffffu, bcar, d);
            if (lane >= d) bcar = fmaf(c, up, bcar);
            c = c * c;
        }
        bc[si] = bcar;
        if (lane == 31) wagg[si][w] = bcar;
    }
    __syncthreads();

    // ---- cross-warp: one segmented 32-lane scan handles 4 rates x 8 warps ----
    if (w == 0) {
        const int gsi = lane >> 3, gl = lane & 7;
        float v = wagg[gsi][gl];
        float tt = (gsi == 0) ? (0.015f * (44100.0f / 512.0f)) :
                   (gsi == 1) ? (0.06f  * (44100.0f / 512.0f)) :
                   (gsi == 2) ? (0.25f  * (44100.0f / 512.0f)) :
                                (1.0f   * (44100.0f / 512.0f));
        float d2 = 2.0f * tt * tt;
        float aa = 1.0f - (sqrtf(1.0f + 2.0f * d2) - 1.0f) / d2;
        float c = aa;
#pragma unroll
        for (int i = 0; i < 9; i++) c = c * c;   // a^512
#pragma unroll
        for (int d = 1; d <= 4; d <<= 1) {
            float up = __shfl_up_sync(0xffffffffu, v, d);
            if (gl >= d) v = fmaf(c, up, v);
            c = c * c;
        }
        wagg[gsi][gl] = v;                       // inclusive warp prefix
    }
    __syncthreads();

    // ---- per-thread incoming state for each rate ----
    float minv[NS];
#pragma unroll
    for (int si = 0; si < NS; si++) {
        float Lprev = __shfl_up_sync(0xffffffffu, bc[si], 1);
        if (tid == 0) {
            minv[si] = xv[0];
        } else {
            float P = (w > 0) ? wagg[si][w - 1] : 0.0f;
            float a16l = fast_exp2((float)(16 * lane) * fast_log2(a[si]));
            minv[si] = fmaf(a16l, P, (lane > 0) ? Lprev : 0.0f);
        }
    }

    // ---- pass 2: recurrence + fused PCEN, staged coalesced stores ----
    // final pow -> polynomial exp2 (off the MUFU pipe; latency-tolerant sink)
#pragma unroll
    for (int si = 0; si < NS; si++) {
        float m = minv[si];
        float* sb = buf[si & 1];
#pragma unroll
        for (int q = 0; q < 4; q++) {
            float t4[4];
#pragma unroll
            for (int e = 0; e < 4; e++) {
                const int k = q * 4 + e;
                m = fmaf(a[si], m, s[si] * xv[k]);
                const float u  = 1e-5f + m;                         // eps + m
                const float sm = fast_exp2(-alpha * fast_log2(u));  // (eps+m)^-alpha
                const float v2 = fmaf(xv[k], sm, delta);            // x*smooth + delta
                t4[e] = poly_exp2(rr * fast_log2(v2)) - delta_r;    // v^r - delta^r
            }
            float4 o; o.x = t4[0]; o.y = t4[1]; o.z = t4[2]; o.w = t4[3];
            *reinterpret_cast<float4*>(&sb[tid * GP + q * 4]) = o;  // own group
        }
        __syncthreads();
        float* orow = out + (((size_t)b * NS + si) * NF + f) * (size_t)NT;
#pragma unroll
        for (int j = 0; j < 4; j++) {
            int Q = j * TPB + tid;
            float4 v = *reinterpret_cast<float4*>(&sb[qaddr(Q)]);
            *reinterpret_cast<float4*>(orow + 4 * Q) = v;           // coalesced STG.128
        }
        // double-buffered: next rate writes the other buffer; the next rate's
        // barrier orders this rate's reads before buffer reuse two rates later
    }
}

extern "C" void kernel_launch(void* const* d_in, const int* in_sizes, int n_in,
                              void* d_out, int out_size) {
    const float* x         = (const float*)d_in[0];
    const float* alpha_log = (const float*)d_in[1];
    const float* delta_log = (const float*)d_in[2];
    const float* r_log     = (const float*)d_in[3];
    float* out             = (float*)d_out;
    (void)in_sizes; (void)n_in; (void)out_size;

    dim3 grid(NBATCH * NF);   // 2048 blocks: one per (b, f) row
    dim3 block(TPB);
    mrpcen_kernel<<<grid, block>>>(x, alpha_log, delta_log, r_log, out);
}